// round 3
// baseline (speedup 1.0000x reference)
#include <cuda_runtime.h>
#include <math.h>

#define N 16384
#define B 16384
#define THREADS 256
#define BLOCKS (N / THREADS)          // 64
#define SCAN_THREADS 1024
#define ITEMS (B / SCAN_THREADS)      // 16

// ---------------- static device scratch (no allocation allowed) ----------------
__device__ int    g_count[B];     // items per bucket
__device__ int    g_start[B];     // exclusive prefix of counts (bucket start)
__device__ int    g_cursor[B];    // scatter cursors (copy of g_start)
__device__ float  g_bsum[B];      // sum of exp(theta) per bucket
__device__ float  g_bsuffix[B];   // exclusive suffix: sum over buckets > b
__device__ float2 g_sorted[N];    // (time, exp(theta)) bucket-sorted
__device__ float  g_acc[2];       // [0]=sum ev*(theta-logS), [1]=sum ev

__device__ __forceinline__ int bucket_of(float t) {
    int b = (int)(t * 16384.0f);          // *2^14 exact, monotone
    if (b < 0) b = 0;
    if (b > B - 1) b = B - 1;
    return b;
}

// ---------------- K0: init ----------------
__global__ void k_init() {
    int i = blockIdx.x * blockDim.x + threadIdx.x;
    g_count[i] = 0;
    g_bsum[i]  = 0.0f;
    if (i < 2) g_acc[i] = 0.0f;
}

// ---------------- K1: histogram ----------------
__global__ void k_hist(const float* __restrict__ risk,
                       const float* __restrict__ time_) {
    int j = blockIdx.x * blockDim.x + threadIdx.x;
    float t = time_[j];
    float e = expf(risk[j]);
    int b = bucket_of(t);
    atomicAdd(&g_count[b], 1);
    atomicAdd(&g_bsum[b], e);
}

// ---------------- K2: scans (single block, 1024 threads, 16 items each) ------
__global__ void k_scan() {
    __shared__ int   s_wi[32];
    __shared__ float s_wf[32];
    int t    = threadIdx.x;
    int lane = t & 31;
    int warp = t >> 5;
    int base = t * ITEMS;

    // ---- pass 1: exclusive prefix of counts -> g_start, g_cursor ----
    int loc[ITEMS];
    int run = 0;
    #pragma unroll
    for (int i = 0; i < ITEMS; ++i) { loc[i] = run; run += g_count[base + i]; }

    int v = run;  // inclusive warp scan of chunk totals
    #pragma unroll
    for (int d = 1; d < 32; d <<= 1) {
        int n = __shfl_up_sync(0xffffffffu, v, d);
        if (lane >= d) v += n;
    }
    if (lane == 31) s_wi[warp] = v;
    __syncthreads();
    if (warp == 0) {
        int w = s_wi[lane];
        #pragma unroll
        for (int d = 1; d < 32; d <<= 1) {
            int n = __shfl_up_sync(0xffffffffu, w, d);
            if (lane >= d) w += n;
        }
        s_wi[lane] = w;
    }
    __syncthreads();
    int warpExcl  = (warp == 0) ? 0 : s_wi[warp - 1];
    int chunkExcl = warpExcl + v - run;
    #pragma unroll
    for (int i = 0; i < ITEMS; ++i) {
        int s = chunkExcl + loc[i];
        g_start[base + i]  = s;
        g_cursor[base + i] = s;
    }
    __syncthreads();

    // ---- pass 2: exclusive suffix of bsum (reversed scan) -> g_bsuffix ----
    float fl[ITEMS];
    float frun = 0.0f;
    #pragma unroll
    for (int i = 0; i < ITEMS; ++i) {
        int b = B - 1 - (base + i);
        fl[i] = frun;
        frun += g_bsum[b];
    }
    float fv = frun;
    #pragma unroll
    for (int d = 1; d < 32; d <<= 1) {
        float n = __shfl_up_sync(0xffffffffu, fv, d);
        if (lane >= d) fv += n;
    }
    if (lane == 31) s_wf[warp] = fv;
    __syncthreads();
    if (warp == 0) {
        float w = s_wf[lane];
        #pragma unroll
        for (int d = 1; d < 32; d <<= 1) {
            float n = __shfl_up_sync(0xffffffffu, w, d);
            if (lane >= d) w += n;
        }
        s_wf[lane] = w;
    }
    __syncthreads();
    float wExclF  = (warp == 0) ? 0.0f : s_wf[warp - 1];
    float cExclF  = wExclF + fv - frun;
    #pragma unroll
    for (int i = 0; i < ITEMS; ++i) {
        int b = B - 1 - (base + i);
        g_bsuffix[b] = cExclF + fl[i];
    }
}

// ---------------- K3: scatter ----------------
__global__ void k_scatter(const float* __restrict__ risk,
                          const float* __restrict__ time_) {
    int j = blockIdx.x * blockDim.x + threadIdx.x;
    float t = time_[j];
    float e = expf(risk[j]);
    int b = bucket_of(t);
    int pos = atomicAdd(&g_cursor[b], 1);
    g_sorted[pos] = make_float2(t, e);
}

// ---------------- K4: per-sample loss + reduce ----------------
__global__ void k_loss(const float* __restrict__ risk,
                       const float* __restrict__ time_,
                       const float* __restrict__ event_) {
    __shared__ float s_num[8];
    __shared__ float s_den[8];
    int i = blockIdx.x * blockDim.x + threadIdx.x;

    float t  = time_[i];
    float th = risk[i];
    float ev = event_[i];
    int   b  = bucket_of(t);

    float S = g_bsuffix[b];                 // buckets strictly above b
    int st  = g_start[b];
    int en  = st + g_count[b];
    for (int p = st; p < en; ++p) {         // exact in-bucket filter (avg 1 iter)
        float2 v = g_sorted[p];
        if (v.x >= t) S += v.y;
    }
    float num = ev * (th - logf(S));
    float den = ev;

    // warp reduce
    #pragma unroll
    for (int d = 16; d > 0; d >>= 1) {
        num += __shfl_down_sync(0xffffffffu, num, d);
        den += __shfl_down_sync(0xffffffffu, den, d);
    }
    int lane = threadIdx.x & 31, warp = threadIdx.x >> 5;
    if (lane == 0) { s_num[warp] = num; s_den[warp] = den; }
    __syncthreads();
    if (warp == 0) {
        num = (lane < 8) ? s_num[lane] : 0.0f;
        den = (lane < 8) ? s_den[lane] : 0.0f;
        #pragma unroll
        for (int d = 4; d > 0; d >>= 1) {
            num += __shfl_down_sync(0xffffffffu, num, d);
            den += __shfl_down_sync(0xffffffffu, den, d);
        }
        if (lane == 0) {
            atomicAdd(&g_acc[0], num);
            atomicAdd(&g_acc[1], den);
        }
    }
}

// ---------------- K5: finalize ----------------
__global__ void k_final(float* __restrict__ out) {
    out[0] = -g_acc[0] / g_acc[1];
}

extern "C" void kernel_launch(void* const* d_in, const int* in_sizes, int n_in,
                              void* d_out, int out_size) {
    const float* risk  = (const float*)d_in[0];
    const float* time_ = (const float*)d_in[1];
    const float* event_= (const float*)d_in[2];
    float* out = (float*)d_out;

    k_init   <<<BLOCKS, THREADS>>>();
    k_hist   <<<BLOCKS, THREADS>>>(risk, time_);
    k_scan   <<<1, SCAN_THREADS>>>();
    k_scatter<<<BLOCKS, THREADS>>>(risk, time_);
    k_loss   <<<BLOCKS, THREADS>>>(risk, time_, event_);
    k_final  <<<1, 1>>>(out);
}